// round 8
// baseline (speedup 1.0000x reference)
#include <cuda_runtime.h>
#include <cuda_bf16.h>

#define N_NODES_MAX 1000000
#define KE_HALF 7.199822675975274f   // 14.399645351950548 / 2

// Per-node z value (index_to_z[species[i]], 1..100 fits in u8). 1 MB.
__device__ unsigned char g_z[N_NODES_MAX];
// a0*d..a3*d, c0..c3 (normalized), p
__device__ float g_params[9];

__device__ __forceinline__ float softplus_f(float x) {
    return log1pf(expf(x));
}

__global__ void prep_kernel(const int* __restrict__ species,
                            const int* __restrict__ index_to_z,
                            const float* __restrict__ a_raw,
                            const float* __restrict__ c_raw,
                            const float* __restrict__ p_raw,
                            const float* __restrict__ d_raw,
                            float* __restrict__ out,
                            int n_nodes) {
    int i = blockIdx.x * blockDim.x + threadIdx.x;

    if (i < 9) {
        float d = softplus_f(d_raw[0]);
        if (i < 4) {
            g_params[i] = softplus_f(a_raw[i]) * d;     // fold d into a_k
        } else if (i < 8) {
            float c0 = softplus_f(c_raw[0]);
            float c1 = softplus_f(c_raw[1]);
            float c2 = softplus_f(c_raw[2]);
            float c3 = softplus_f(c_raw[3]);
            float inv_s = 1.0f / (c0 + c1 + c2 + c3);
            g_params[i] = softplus_f(c_raw[i - 4]) * inv_s;
        } else {
            g_params[8] = softplus_f(p_raw[0]);         // p
        }
    }

    if (i < n_nodes) {
        out[i] = 0.0f;  // zero-init accumulator (harness poisons d_out)
        g_z[i] = (unsigned char)index_to_z[species[i]];
    }
}

// Full per-edge energy from z values (all math, no memory).
__device__ __forceinline__ float edge_compute(float dd, float cc,
                                              float zi, float zj,
                                              float a0, float a1, float a2, float a3,
                                              float c0, float c1, float c2, float c3,
                                              float p) {
    float zpi = __expf(p * __logf(zi));   // z >= 1 so log safe
    float zpj = __expf(p * __logf(zj));

    float x = __fdividef(KE_HALF * cc * zi * zj, dd + 1e-8f);

    float t = dd * (zpi + zpj);           // a_k pre-scaled by d

    float y = c0 * __expf(-a0 * t)
            + c1 * __expf(-a1 * t)
            + c2 * __expf(-a2 * t)
            + c3 * __expf(-a3 * t);

    float sd = dd * (1.0f / 1.5f);
    float s1 = 1.0f - sd;
    sd = fmaxf(sd, 1e-8f);
    s1 = fmaxf(s1, 1e-8f);
    float e = __expf(__fdividef(1.0f, s1) - __fdividef(1.0f, sd));
    float w = __fdividef(1.0f, 1.0f + e);

    return w * x * y;
}

// Persistent grid-stride kernel with software-pipelined stream prefetch.
__global__ __launch_bounds__(256)
void edge_kernel(const float4* __restrict__ dist4,
                 const float4* __restrict__ cut4,
                 const int4* __restrict__ snd4,
                 const int4* __restrict__ rcv4,
                 float* __restrict__ out,
                 int n4, int n_tail_base, int n_edges) {
    const int tid0   = blockIdx.x * blockDim.x + threadIdx.x;
    const int stride = gridDim.x * blockDim.x;

    const float a0 = g_params[0], a1 = g_params[1], a2 = g_params[2], a3 = g_params[3];
    const float c0 = g_params[4], c1 = g_params[5], c2 = g_params[6], c3 = g_params[7];
    const float p  = g_params[8];

    int i = tid0;
    if (i < n4) {
        // prologue: load first iteration's streams
        float4 dv = __ldcs(&dist4[i]);
        float4 cv = __ldcs(&cut4[i]);
        int4   sv = __ldcs(&snd4[i]);
        int4   rv = __ldcs(&rcv4[i]);

        for (;;) {
            const int inext = i + stride;
            const bool has_next = inext < n4;

            // prefetch next iteration's streams BEFORE current compute:
            // hides the coalesced-load latency behind gathers + MUFU work.
            float4 dv_n, cv_n;
            int4   sv_n, rv_n;
            if (has_next) {
                dv_n = __ldcs(&dist4[inext]);
                cv_n = __ldcs(&cut4[inext]);
                sv_n = __ldcs(&snd4[inext]);
                rv_n = __ldcs(&rcv4[inext]);
            }

            // 8 random u8 gathers, back-to-back
            float zj0 = (float)g_z[sv.x];
            float zj1 = (float)g_z[sv.y];
            float zj2 = (float)g_z[sv.z];
            float zj3 = (float)g_z[sv.w];
            float zi0 = (float)g_z[rv.x];
            float zi1 = (float)g_z[rv.y];
            float zi2 = (float)g_z[rv.z];
            float zi3 = (float)g_z[rv.w];

            float e0 = edge_compute(dv.x, cv.x, zi0, zj0, a0,a1,a2,a3, c0,c1,c2,c3, p);
            float e1 = edge_compute(dv.y, cv.y, zi1, zj1, a0,a1,a2,a3, c0,c1,c2,c3, p);
            float e2 = edge_compute(dv.z, cv.z, zi2, zj2, a0,a1,a2,a3, c0,c1,c2,c3, p);
            float e3 = edge_compute(dv.w, cv.w, zi3, zj3, a0,a1,a2,a3, c0,c1,c2,c3, p);

            atomicAdd(&out[rv.x], e0);
            atomicAdd(&out[rv.y], e1);
            atomicAdd(&out[rv.z], e2);
            atomicAdd(&out[rv.w], e3);

            if (!has_next) break;
            i = inext;
            dv = dv_n; cv = cv_n; sv = sv_n; rv = rv_n;
        }
    }

    // tail (n_edges % 4): distribute over first warp of the grid
    {
        int t = n_tail_base + tid0;
        if (t < n_edges && tid0 < 32) {
            const float* dist = (const float*)dist4;
            const float* cut  = (const float*)cut4;
            const int*   snd  = (const int*)snd4;
            const int*   rcv  = (const int*)rcv4;
            float zi = (float)g_z[rcv[t]];
            float zj = (float)g_z[snd[t]];
            float en = edge_compute(dist[t], cut[t], zi, zj, a0,a1,a2,a3, c0,c1,c2,c3, p);
            atomicAdd(&out[rcv[t]], en);
        }
    }
}

extern "C" void kernel_launch(void* const* d_in, const int* in_sizes, int n_in,
                              void* d_out, int out_size) {
    const int*   node_species = (const int*)d_in[0];
    const float* distances    = (const float*)d_in[1];
    const float* cutoffs      = (const float*)d_in[2];
    const int*   senders      = (const int*)d_in[3];
    const int*   receivers    = (const int*)d_in[4];
    const int*   index_to_z   = (const int*)d_in[5];
    const float* a_raw        = (const float*)d_in[6];
    const float* c_raw        = (const float*)d_in[7];
    const float* p_raw        = (const float*)d_in[8];
    const float* d_raw        = (const float*)d_in[9];
    float* out = (float*)d_out;

    int n_nodes = in_sizes[0];
    int n_edges = in_sizes[1];

    {
        int threads = 256;
        int blocks = (n_nodes + threads - 1) / threads;
        prep_kernel<<<blocks, threads>>>(node_species, index_to_z,
                                         a_raw, c_raw, p_raw, d_raw,
                                         out, n_nodes);
    }
    {
        int n4 = n_edges >> 2;
        int threads = 256;
        // persistent: ~8 CTAs/SM on 148 SMs (152 on GB300; 148 is safe either way)
        int blocks = 148 * 8;
        int needed = (n4 + threads - 1) / threads;
        if (blocks > needed) blocks = needed;
        if (blocks == 0) blocks = 1;
        edge_kernel<<<blocks, threads>>>((const float4*)distances,
                                         (const float4*)cutoffs,
                                         (const int4*)senders,
                                         (const int4*)receivers,
                                         out, n4, n4 << 2, n_edges);
    }
}

// round 10
// speedup vs baseline: 1.1126x; 1.1126x over previous
#include <cuda_runtime.h>
#include <cuda_bf16.h>

#define N_NODES_MAX 1000000
#define KE_HALF 7.199822675975274f   // 14.399645351950548 / 2

// Per-node z value (index_to_z[species[i]], 1..100 fits in u8). 1 MB, L2-resident.
__device__ unsigned char g_z[N_NODES_MAX];
// a0*d..a3*d, c0..c3 (normalized), p
__device__ float g_params[9];

__device__ __forceinline__ float softplus_f(float x) {
    return log1pf(expf(x));
}

__global__ void prep_kernel(const int* __restrict__ species,
                            const int* __restrict__ index_to_z,
                            const float* __restrict__ a_raw,
                            const float* __restrict__ c_raw,
                            const float* __restrict__ p_raw,
                            const float* __restrict__ d_raw,
                            float* __restrict__ out,
                            int n_nodes) {
    int i = blockIdx.x * blockDim.x + threadIdx.x;

    if (i < 9) {
        float d = softplus_f(d_raw[0]);
        if (i < 4) {
            g_params[i] = softplus_f(a_raw[i]) * d;     // fold d into a_k
        } else if (i < 8) {
            float c0 = softplus_f(c_raw[0]);
            float c1 = softplus_f(c_raw[1]);
            float c2 = softplus_f(c_raw[2]);
            float c3 = softplus_f(c_raw[3]);
            float inv_s = 1.0f / (c0 + c1 + c2 + c3);
            g_params[i] = softplus_f(c_raw[i - 4]) * inv_s;
        } else {
            g_params[8] = softplus_f(p_raw[0]);         // p
        }
    }

    if (i < n_nodes) {
        out[i] = 0.0f;  // zero-init accumulator (harness poisons d_out)
        g_z[i] = (unsigned char)index_to_z[species[i]];
    }
}

// Full per-edge energy from z values (all math, no memory).
__device__ __forceinline__ float edge_compute(float dd, float cc,
                                              float zi, float zj,
                                              float a0, float a1, float a2, float a3,
                                              float c0, float c1, float c2, float c3,
                                              float p) {
    float zpi = __expf(p * __logf(zi));   // z >= 1 so log safe
    float zpj = __expf(p * __logf(zj));

    float x = __fdividef(KE_HALF * cc * zi * zj, dd + 1e-8f);

    float t = dd * (zpi + zpj);           // a_k pre-scaled by d

    float y = c0 * __expf(-a0 * t)
            + c1 * __expf(-a1 * t)
            + c2 * __expf(-a2 * t)
            + c3 * __expf(-a3 * t);

    float sd = dd * (1.0f / 1.5f);
    float s1 = 1.0f - sd;
    sd = fmaxf(sd, 1e-8f);
    s1 = fmaxf(s1, 1e-8f);
    float e = __expf(__fdividef(1.0f, s1) - __fdividef(1.0f, sd));
    float w = __fdividef(1.0f, 1.0f + e);

    return w * x * y;
}

__global__ __launch_bounds__(128)
void edge_kernel(const float4* __restrict__ dist4,
                 const float4* __restrict__ cut4,
                 const int4* __restrict__ snd4,
                 const int4* __restrict__ rcv4,
                 float* __restrict__ out,
                 int n4, int n_tail_base, int n_edges) {
    int i = blockIdx.x * blockDim.x + threadIdx.x;

    float a0 = g_params[0], a1 = g_params[1], a2 = g_params[2], a3 = g_params[3];
    float c0 = g_params[4], c1 = g_params[5], c2 = g_params[6], c3 = g_params[7];
    float p  = g_params[8];

    if (i < n4) {
        // Streaming reads, evict-first
        float4 dv = __ldcs(&dist4[i]);
        float4 cv = __ldcs(&cut4[i]);
        int4   sv = __ldcs(&snd4[i]);
        int4   rv = __ldcs(&rcv4[i]);

        // 8 random u8 gathers issued back-to-back
        float zj0 = (float)g_z[sv.x];
        float zj1 = (float)g_z[sv.y];
        float zj2 = (float)g_z[sv.z];
        float zj3 = (float)g_z[sv.w];
        float zi0 = (float)g_z[rv.x];
        float zi1 = (float)g_z[rv.y];
        float zi2 = (float)g_z[rv.z];
        float zi3 = (float)g_z[rv.w];

        float e0 = edge_compute(dv.x, cv.x, zi0, zj0, a0,a1,a2,a3, c0,c1,c2,c3, p);
        float e1 = edge_compute(dv.y, cv.y, zi1, zj1, a0,a1,a2,a3, c0,c1,c2,c3, p);
        float e2 = edge_compute(dv.z, cv.z, zi2, zj2, a0,a1,a2,a3, c0,c1,c2,c3, p);
        float e3 = edge_compute(dv.w, cv.w, zi3, zj3, a0,a1,a2,a3, c0,c1,c2,c3, p);

        atomicAdd(&out[rv.x], e0);
        atomicAdd(&out[rv.y], e1);
        atomicAdd(&out[rv.z], e2);
        atomicAdd(&out[rv.w], e3);
    }

    // tail (n_edges % 4): distribute over the grid's first warp
    {
        int t = n_tail_base + i;
        if (t < n_edges && i < 32) {
            const float* dist = (const float*)dist4;
            const float* cut  = (const float*)cut4;
            const int*   snd  = (const int*)snd4;
            const int*   rcv  = (const int*)rcv4;
            float zi = (float)g_z[rcv[t]];
            float zj = (float)g_z[snd[t]];
            float en = edge_compute(dist[t], cut[t], zi, zj, a0,a1,a2,a3, c0,c1,c2,c3, p);
            atomicAdd(&out[rcv[t]], en);
        }
    }
}

extern "C" void kernel_launch(void* const* d_in, const int* in_sizes, int n_in,
                              void* d_out, int out_size) {
    const int*   node_species = (const int*)d_in[0];
    const float* distances    = (const float*)d_in[1];
    const float* cutoffs      = (const float*)d_in[2];
    const int*   senders      = (const int*)d_in[3];
    const int*   receivers    = (const int*)d_in[4];
    const int*   index_to_z   = (const int*)d_in[5];
    const float* a_raw        = (const float*)d_in[6];
    const float* c_raw        = (const float*)d_in[7];
    const float* p_raw        = (const float*)d_in[8];
    const float* d_raw        = (const float*)d_in[9];
    float* out = (float*)d_out;

    int n_nodes = in_sizes[0];
    int n_edges = in_sizes[1];

    {
        int threads = 256;
        int blocks = (n_nodes + threads - 1) / threads;
        prep_kernel<<<blocks, threads>>>(node_species, index_to_z,
                                         a_raw, c_raw, p_raw, d_raw,
                                         out, n_nodes);
    }
    {
        int n4 = n_edges >> 2;
        int threads = 128;
        int blocks = (n4 + threads - 1) / threads;
        if (blocks == 0) blocks = 1;
        edge_kernel<<<blocks, threads>>>((const float4*)distances,
                                         (const float4*)cutoffs,
                                         (const int4*)senders,
                                         (const int4*)receivers,
                                         out, n4, n4 << 2, n_edges);
    }
}

// round 12
// speedup vs baseline: 1.1158x; 1.0029x over previous
#include <cuda_runtime.h>
#include <cuda_bf16.h>

#define N_NODES_MAX 1000000
#define KE_HALF 7.199822675975274f   // 14.399645351950548 / 2

// Per-node z value (index_to_z[species[i]], 1..100 fits in u8). 1 MB, L2-resident.
__device__ unsigned char g_z[N_NODES_MAX];
// a0*d..a3*d, c0..c3 (normalized), p
__device__ float g_params[9];

__device__ __forceinline__ float softplus_f(float x) {
    return log1pf(expf(x));
}

// Vectorized prep: 4 nodes per thread (int4 species read, packed u8x4 z store,
// float4 out zeroing). ~9 MB total traffic -> DRAM-bound ~3 us.
__global__ void prep_kernel(const int* __restrict__ species,
                            const int* __restrict__ index_to_z,
                            const float* __restrict__ a_raw,
                            const float* __restrict__ c_raw,
                            const float* __restrict__ p_raw,
                            const float* __restrict__ d_raw,
                            float* __restrict__ out,
                            int n_nodes, int n_nodes4) {
    int i = blockIdx.x * blockDim.x + threadIdx.x;

    if (i < 9) {
        float d = softplus_f(d_raw[0]);
        if (i < 4) {
            g_params[i] = softplus_f(a_raw[i]) * d;     // fold d into a_k
        } else if (i < 8) {
            float c0 = softplus_f(c_raw[0]);
            float c1 = softplus_f(c_raw[1]);
            float c2 = softplus_f(c_raw[2]);
            float c3 = softplus_f(c_raw[3]);
            float inv_s = 1.0f / (c0 + c1 + c2 + c3);
            g_params[i] = softplus_f(c_raw[i - 4]) * inv_s;
        } else {
            g_params[8] = softplus_f(p_raw[0]);         // p
        }
    }

    if (i < n_nodes4) {
        int4 sp = ((const int4*)species)[i];
        unsigned int packed =
              (unsigned int)(index_to_z[sp.x] & 0xFF)
            | ((unsigned int)(index_to_z[sp.y] & 0xFF) << 8)
            | ((unsigned int)(index_to_z[sp.z] & 0xFF) << 16)
            | ((unsigned int)(index_to_z[sp.w] & 0xFF) << 24);
        ((unsigned int*)g_z)[i] = packed;
        ((float4*)out)[i] = make_float4(0.f, 0.f, 0.f, 0.f);
    }

    // node-count tail (n_nodes % 4)
    int t = n_nodes4 * 4 + i;
    if (t < n_nodes && i < 4) {
        g_z[t] = (unsigned char)index_to_z[species[t]];
        out[t] = 0.0f;
    }
}

// Full per-edge energy from z values (all math, no memory).
__device__ __forceinline__ float edge_compute(float dd, float cc,
                                              float zi, float zj,
                                              float a0, float a1, float a2, float a3,
                                              float c0, float c1, float c2, float c3,
                                              float p) {
    float zpi = __expf(p * __logf(zi));   // z >= 1 so log safe
    float zpj = __expf(p * __logf(zj));

    float x = __fdividef(KE_HALF * cc * zi * zj, dd + 1e-8f);

    float t = dd * (zpi + zpj);           // a_k pre-scaled by d

    float y = c0 * __expf(-a0 * t)
            + c1 * __expf(-a1 * t)
            + c2 * __expf(-a2 * t)
            + c3 * __expf(-a3 * t);

    float sd = dd * (1.0f / 1.5f);
    float s1 = 1.0f - sd;
    sd = fmaxf(sd, 1e-8f);
    s1 = fmaxf(s1, 1e-8f);
    float e = __expf(__fdividef(1.0f, s1) - __fdividef(1.0f, sd));
    float w = __fdividef(1.0f, 1.0f + e);

    return w * x * y;
}

__global__ __launch_bounds__(128)
void edge_kernel(const float4* __restrict__ dist4,
                 const float4* __restrict__ cut4,
                 const int4* __restrict__ snd4,
                 const int4* __restrict__ rcv4,
                 float* __restrict__ out,
                 int n4, int n_tail_base, int n_edges) {
    int i = blockIdx.x * blockDim.x + threadIdx.x;

    float a0 = g_params[0], a1 = g_params[1], a2 = g_params[2], a3 = g_params[3];
    float c0 = g_params[4], c1 = g_params[5], c2 = g_params[6], c3 = g_params[7];
    float p  = g_params[8];

    if (i < n4) {
        // Streaming reads, evict-first
        float4 dv = __ldcs(&dist4[i]);
        float4 cv = __ldcs(&cut4[i]);
        int4   sv = __ldcs(&snd4[i]);
        int4   rv = __ldcs(&rcv4[i]);

        // 8 random u8 gathers issued back-to-back (read-only path)
        float zj0 = (float)__ldg(&g_z[sv.x]);
        float zj1 = (float)__ldg(&g_z[sv.y]);
        float zj2 = (float)__ldg(&g_z[sv.z]);
        float zj3 = (float)__ldg(&g_z[sv.w]);
        float zi0 = (float)__ldg(&g_z[rv.x]);
        float zi1 = (float)__ldg(&g_z[rv.y]);
        float zi2 = (float)__ldg(&g_z[rv.z]);
        float zi3 = (float)__ldg(&g_z[rv.w]);

        float e0 = edge_compute(dv.x, cv.x, zi0, zj0, a0,a1,a2,a3, c0,c1,c2,c3, p);
        float e1 = edge_compute(dv.y, cv.y, zi1, zj1, a0,a1,a2,a3, c0,c1,c2,c3, p);
        float e2 = edge_compute(dv.z, cv.z, zi2, zj2, a0,a1,a2,a3, c0,c1,c2,c3, p);
        float e3 = edge_compute(dv.w, cv.w, zi3, zj3, a0,a1,a2,a3, c0,c1,c2,c3, p);

        atomicAdd(&out[rv.x], e0);
        atomicAdd(&out[rv.y], e1);
        atomicAdd(&out[rv.z], e2);
        atomicAdd(&out[rv.w], e3);
    }

    // tail (n_edges % 4): distribute over the grid's first warp
    {
        int t = n_tail_base + i;
        if (t < n_edges && i < 32) {
            const float* dist = (const float*)dist4;
            const float* cut  = (const float*)cut4;
            const int*   snd  = (const int*)snd4;
            const int*   rcv  = (const int*)rcv4;
            float zi = (float)g_z[rcv[t]];
            float zj = (float)g_z[snd[t]];
            float en = edge_compute(dist[t], cut[t], zi, zj, a0,a1,a2,a3, c0,c1,c2,c3, p);
            atomicAdd(&out[rcv[t]], en);
        }
    }
}

extern "C" void kernel_launch(void* const* d_in, const int* in_sizes, int n_in,
                              void* d_out, int out_size) {
    const int*   node_species = (const int*)d_in[0];
    const float* distances    = (const float*)d_in[1];
    const float* cutoffs      = (const float*)d_in[2];
    const int*   senders      = (const int*)d_in[3];
    const int*   receivers    = (const int*)d_in[4];
    const int*   index_to_z   = (const int*)d_in[5];
    const float* a_raw        = (const float*)d_in[6];
    const float* c_raw        = (const float*)d_in[7];
    const float* p_raw        = (const float*)d_in[8];
    const float* d_raw        = (const float*)d_in[9];
    float* out = (float*)d_out;

    int n_nodes = in_sizes[0];
    int n_edges = in_sizes[1];

    {
        int n_nodes4 = n_nodes >> 2;
        int threads = 256;
        int blocks = (n_nodes4 + threads - 1) / threads;
        if (blocks == 0) blocks = 1;
        prep_kernel<<<blocks, threads>>>(node_species, index_to_z,
                                         a_raw, c_raw, p_raw, d_raw,
                                         out, n_nodes, n_nodes4);
    }
    {
        int n4 = n_edges >> 2;
        int threads = 128;
        int blocks = (n4 + threads - 1) / threads;
        if (blocks == 0) blocks = 1;
        edge_kernel<<<blocks, threads>>>((const float4*)distances,
                                         (const float4*)cutoffs,
                                         (const int4*)senders,
                                         (const int4*)receivers,
                                         out, n4, n4 << 2, n_edges);
    }
}